// round 6
// baseline (speedup 1.0000x reference)
#include <cuda_runtime.h>
#include <cstdint>

#define SQ 2048
#define DM 4096
#define NH 32
#define HD 128

// Scratch (allocation-free rule: __device__ globals). 4 x 32 MB.
__device__ float g_q[(size_t)SQ * DM];
__device__ float g_k[(size_t)SQ * DM];
__device__ float g_v[(size_t)SQ * DM];
__device__ float g_att[(size_t)SQ * DM];

__device__ __forceinline__ float to_tf32(float x) {
    uint32_t u;
    asm("cvt.rna.tf32.f32 %0, %1;" : "=r"(u) : "f"(x));
    return __uint_as_float(u);
}

__device__ __forceinline__ void mma8(float* d, const uint32_t* a, const uint32_t* b) {
    asm volatile(
        "mma.sync.aligned.m16n8k8.row.col.f32.tf32.tf32.f32 "
        "{%0,%1,%2,%3}, {%4,%5,%6,%7}, {%8,%9}, {%0,%1,%2,%3};"
        : "+f"(d[0]), "+f"(d[1]), "+f"(d[2]), "+f"(d[3])
        : "r"(a[0]), "r"(a[1]), "r"(a[2]), "r"(a[3]), "r"(b[0]), "r"(b[1]));
}

// ============================================================================
// Dense TF32 GEMM: C[M,N] = alpha * A[M,K] @ B[K,N], row-major, 128x128 tile.
// ROPE=true: apply rotary embedding in the epilogue (pairs = adjacent cols,
// which is exactly the (c0,c1)/(c2,c3) layout of the m16n8k8 C fragment).
// ============================================================================
template <bool ROPE>
__global__ void __launch_bounds__(256) gemm_tf32(
    const float* __restrict__ A, const float* __restrict__ B, float* __restrict__ C,
    int K, int lda, int ldb, int ldc, float alpha,
    const float* __restrict__ fc, const float* __restrict__ fs)
{
    __shared__ float As[16][136];   // [k][m], pad 8 -> conflict-free frag loads
    __shared__ float Bs[16][136];   // [k][n]

    const int bm = blockIdx.y * 128;
    const int bn = blockIdx.x * 128;
    const int tid  = threadIdx.x;
    const int lane = tid & 31;
    const int warp = tid >> 5;
    const int wm = (warp & 3) * 32;   // 4 warps along M
    const int wn = (warp >> 2) * 64;  // 2 warps along N
    const int g  = lane >> 2;         // groupID 0..7
    const int t4 = lane & 3;          // 0..3

    float acc[2][8][4];
#pragma unroll
    for (int a = 0; a < 2; a++)
#pragma unroll
        for (int b = 0; b < 8; b++)
#pragma unroll
            for (int c = 0; c < 4; c++) acc[a][b][c] = 0.f;

    for (int k0 = 0; k0 < K; k0 += 16) {
#pragma unroll
        for (int it = 0; it < 2; ++it) {
            int f   = tid + it * 256;          // 0..511 float4 slots
            int row = f >> 2;                  // 0..127
            int kc  = (f & 3) << 2;            // 0,4,8,12
            float4 v4 = *reinterpret_cast<const float4*>(
                A + (long long)(bm + row) * lda + (k0 + kc));
            As[kc + 0][row] = to_tf32(v4.x);
            As[kc + 1][row] = to_tf32(v4.y);
            As[kc + 2][row] = to_tf32(v4.z);
            As[kc + 3][row] = to_tf32(v4.w);
        }
#pragma unroll
        for (int it = 0; it < 2; ++it) {
            int f    = tid + it * 256;
            int krow = f >> 5;                 // 0..15
            int col  = (f & 31) << 2;          // 0..124
            float4 v4 = *reinterpret_cast<const float4*>(
                B + (long long)(k0 + krow) * ldb + (bn + col));
            float4 w4;
            w4.x = to_tf32(v4.x); w4.y = to_tf32(v4.y);
            w4.z = to_tf32(v4.z); w4.w = to_tf32(v4.w);
            *reinterpret_cast<float4*>(&Bs[krow][col]) = w4;
        }
        __syncthreads();

#pragma unroll
        for (int kk = 0; kk < 16; kk += 8) {
            uint32_t af[2][4], bf[8][2];
#pragma unroll
            for (int mt = 0; mt < 2; ++mt) {
                int r = wm + mt * 16 + g;
                af[mt][0] = __float_as_uint(As[kk + t4][r]);
                af[mt][1] = __float_as_uint(As[kk + t4][r + 8]);
                af[mt][2] = __float_as_uint(As[kk + t4 + 4][r]);
                af[mt][3] = __float_as_uint(As[kk + t4 + 4][r + 8]);
            }
#pragma unroll
            for (int nt = 0; nt < 8; ++nt) {
                int c = wn + nt * 8 + g;
                bf[nt][0] = __float_as_uint(Bs[kk + t4][c]);
                bf[nt][1] = __float_as_uint(Bs[kk + t4 + 4][c]);
            }
#pragma unroll
            for (int mt = 0; mt < 2; ++mt)
#pragma unroll
                for (int nt = 0; nt < 8; ++nt)
                    mma8(acc[mt][nt], af[mt], bf[nt]);
        }
        __syncthreads();
    }

    // ---- epilogue (optionally fused RoPE: pairs (even,odd col) == (c0,c1))
#pragma unroll
    for (int mt = 0; mt < 2; ++mt)
#pragma unroll
        for (int nt = 0; nt < 8; ++nt) {
            int r = bm + wm + mt * 16 + g;
            int c = bn + wn + nt * 8 + (t4 << 1);
            float x0 = alpha * acc[mt][nt][0];
            float x1 = alpha * acc[mt][nt][1];
            float x2 = alpha * acc[mt][nt][2];
            float x3 = alpha * acc[mt][nt][3];
            if (ROPE) {
                int fi = (c & (HD - 1)) >> 1;      // freq index within head
                float c0 = fc[(long long)r * (HD / 2) + fi];
                float s0 = fs[(long long)r * (HD / 2) + fi];
                float c1 = fc[(long long)(r + 8) * (HD / 2) + fi];
                float s1 = fs[(long long)(r + 8) * (HD / 2) + fi];
                float y0 = x0 * c0 - x1 * s0;
                float y1 = x0 * s0 + x1 * c0;
                float y2 = x2 * c1 - x3 * s1;
                float y3 = x2 * s1 + x3 * c1;
                x0 = y0; x1 = y1; x2 = y2; x3 = y3;
            }
            float2 v;
            v.x = x0; v.y = x1;
            *reinterpret_cast<float2*>(C + (long long)r * ldc + c) = v;
            v.x = x2; v.y = x3;
            *reinterpret_cast<float2*>(C + (long long)(r + 8) * ldc + c) = v;
        }
}

// ============================================================================
// Fused flash attention (causal), tf32 MMA.
// Grid: (SQ/128, NH). Block: 256 (8 warps; warp w owns query rows w*16..+15).
// Dynamic smem: Qs[d][q], Ks[d][j], Vs[j][d] each 128x136 fp32 -> 204 KB.
// ============================================================================
#define ASTRIDE 136
#define ATN_SMEM (3 * 128 * ASTRIDE * (int)sizeof(float))

__global__ void __launch_bounds__(256, 1) attn_fused(
    const float* __restrict__ Q, const float* __restrict__ K,
    const float* __restrict__ V, float* __restrict__ Oa)
{
    extern __shared__ float smem[];
    float* Qs = smem;                      // [d][q]
    float* Ks = smem + 128 * ASTRIDE;      // [d][j]
    float* Vs = smem + 2 * 128 * ASTRIDE;  // [j][d]

    const int h  = blockIdx.y;
    const int i0 = (SQ / 128 - 1 - (int)blockIdx.x) * 128;  // heavy tiles first
    const int tid  = threadIdx.x;
    const int lane = tid & 31;
    const int warp = tid >> 5;
    const int g  = lane >> 2;
    const int t4 = lane & 3;
    const int w16 = warp * 16;
    const float scale = 0.08838834764831845f;   // 1/sqrt(128)

    // ---- load Q tile (transposed to [d][q]) once
#pragma unroll
    for (int it = 0; it < 16; ++it) {
        int f   = tid + it * 256;          // 0..4095
        int row = f >> 5;                  // query 0..127
        int c4  = (f & 31) << 2;           // d 0..124
        float4 v4 = *reinterpret_cast<const float4*>(
            Q + (size_t)(i0 + row) * DM + h * HD + c4);
        Qs[(c4 + 0) * ASTRIDE + row] = to_tf32(v4.x);
        Qs[(c4 + 1) * ASTRIDE + row] = to_tf32(v4.y);
        Qs[(c4 + 2) * ASTRIDE + row] = to_tf32(v4.z);
        Qs[(c4 + 3) * ASTRIDE + row] = to_tf32(v4.w);
    }

    float o[16][4];
#pragma unroll
    for (int n = 0; n < 16; ++n)
#pragma unroll
        for (int c = 0; c < 4; ++c) o[n][c] = 0.f;
    float m0 = -1e30f, m1 = -1e30f, l0 = 0.f, l1 = 0.f;

    const int r0g = i0 + w16 + g;          // global query row (g); +8 for other
    const unsigned FULL = 0xffffffffu;

    for (int j0 = 0; j0 <= i0; j0 += 128) {
        __syncthreads();   // previous iteration's smem reads done (also covers Q load)
        // ---- stage K (transposed) and V (natural) tiles
#pragma unroll
        for (int it = 0; it < 16; ++it) {
            int f   = tid + it * 256;
            int row = f >> 5;              // key 0..127
            int c4  = (f & 31) << 2;
            float4 kv = *reinterpret_cast<const float4*>(
                K + (size_t)(j0 + row) * DM + h * HD + c4);
            Ks[(c4 + 0) * ASTRIDE + row] = to_tf32(kv.x);
            Ks[(c4 + 1) * ASTRIDE + row] = to_tf32(kv.y);
            Ks[(c4 + 2) * ASTRIDE + row] = to_tf32(kv.z);
            Ks[(c4 + 3) * ASTRIDE + row] = to_tf32(kv.w);
            float4 vv = *reinterpret_cast<const float4*>(
                V + (size_t)(j0 + row) * DM + h * HD + c4);
            float4 w4;
            w4.x = to_tf32(vv.x); w4.y = to_tf32(vv.y);
            w4.z = to_tf32(vv.z); w4.w = to_tf32(vv.w);
            *reinterpret_cast<float4*>(&Vs[row * ASTRIDE + c4]) = w4;
        }
        __syncthreads();

        // ---- S = Q @ K^T  (warp: 16 rows x 128 keys)
        float s[16][4];
#pragma unroll
        for (int n = 0; n < 16; ++n)
#pragma unroll
            for (int c = 0; c < 4; ++c) s[n][c] = 0.f;

#pragma unroll
        for (int kk = 0; kk < 128; kk += 8) {
            uint32_t af[4];
            af[0] = __float_as_uint(Qs[(kk + t4) * ASTRIDE + w16 + g]);
            af[1] = __float_as_uint(Qs[(kk + t4) * ASTRIDE + w16 + g + 8]);
            af[2] = __float_as_uint(Qs[(kk + t4 + 4) * ASTRIDE + w16 + g]);
            af[3] = __float_as_uint(Qs[(kk + t4 + 4) * ASTRIDE + w16 + g + 8]);
#pragma unroll
            for (int n = 0; n < 16; ++n) {
                uint32_t bf[2];
                bf[0] = __float_as_uint(Ks[(kk + t4) * ASTRIDE + n * 8 + g]);
                bf[1] = __float_as_uint(Ks[(kk + t4 + 4) * ASTRIDE + n * 8 + g]);
                mma8(s[n], af, bf);
            }
        }

        // ---- scale + causal mask (only the diagonal tile needs masking)
        const bool diag = (j0 == i0);
#pragma unroll
        for (int n = 0; n < 16; ++n) {
            int c = j0 + n * 8 + (t4 << 1);
            s[n][0] *= scale; s[n][1] *= scale;
            s[n][2] *= scale; s[n][3] *= scale;
            if (diag) {
                if (c     > r0g)     s[n][0] = -1e30f;
                if (c + 1 > r0g)     s[n][1] = -1e30f;
                if (c     > r0g + 8) s[n][2] = -1e30f;
                if (c + 1 > r0g + 8) s[n][3] = -1e30f;
            }
        }

        // ---- online softmax (rows r0g and r0g+8; stats shared across quad)
        float tm0 = -1e30f, tm1 = -1e30f;
#pragma unroll
        for (int n = 0; n < 16; ++n) {
            tm0 = fmaxf(tm0, fmaxf(s[n][0], s[n][1]));
            tm1 = fmaxf(tm1, fmaxf(s[n][2], s[n][3]));
        }
        tm0 = fmaxf(tm0, __shfl_xor_sync(FULL, tm0, 1));
        tm0 = fmaxf(tm0, __shfl_xor_sync(FULL, tm0, 2));
        tm1 = fmaxf(tm1, __shfl_xor_sync(FULL, tm1, 1));
        tm1 = fmaxf(tm1, __shfl_xor_sync(FULL, tm1, 2));
        float nm0 = fmaxf(m0, tm0), nm1 = fmaxf(m1, tm1);
        float a0 = __expf(m0 - nm0), a1 = __expf(m1 - nm1);
        m0 = nm0; m1 = nm1;

        float ts0 = 0.f, ts1 = 0.f;
#pragma unroll
        for (int n = 0; n < 16; ++n) {
            s[n][0] = __expf(s[n][0] - m0);
            s[n][1] = __expf(s[n][1] - m0);
            s[n][2] = __expf(s[n][2] - m1);
            s[n][3] = __expf(s[n][3] - m1);
            ts0 += s[n][0] + s[n][1];
            ts1 += s[n][2] + s[n][3];
        }
        ts0 += __shfl_xor_sync(FULL, ts0, 1);
        ts0 += __shfl_xor_sync(FULL, ts0, 2);
        ts1 += __shfl_xor_sync(FULL, ts1, 1);
        ts1 += __shfl_xor_sync(FULL, ts1, 2);
        l0 = l0 * a0 + ts0;
        l1 = l1 * a1 + ts1;
#pragma unroll
        for (int n = 0; n < 16; ++n) {
            o[n][0] *= a0; o[n][1] *= a0;
            o[n][2] *= a1; o[n][3] *= a1;
        }

        // ---- O += P @ V   (P fragments built from S C-frags via shuffles)
        const int base = lane & 28;            // 4*g
        const int sl0 = base + (t4 >> 1);
        const int sl1 = sl0 + 2;
        const bool odd = (t4 & 1);
#pragma unroll
        for (int n = 0; n < 16; ++n) {         // k-step over 8 keys
            float pa = __shfl_sync(FULL, s[n][0], sl0);
            float pb = __shfl_sync(FULL, s[n][1], sl0);
            float pc = __shfl_sync(FULL, s[n][2], sl0);
            float pd = __shfl_sync(FULL, s[n][3], sl0);
            float pe = __shfl_sync(FULL, s[n][0], sl1);
            float pf = __shfl_sync(FULL, s[n][1], sl1);
            float pg = __shfl_sync(FULL, s[n][2], sl1);
            float ph = __shfl_sync(FULL, s[n][3], sl1);
            uint32_t af[4];
            af[0] = __float_as_uint(to_tf32(odd ? pb : pa));  // P[g][k+t]
            af[1] = __float_as_uint(to_tf32(odd ? pd : pc));  // P[g+8][k+t]
            af[2] = __float_as_uint(to_tf32(odd ? pf : pe));  // P[g][k+t+4]
            af[3] = __float_as_uint(to_tf32(odd ? ph : pg));  // P[g+8][k+t+4]
            int kk = n * 8;
#pragma unroll
            for (int nn = 0; nn < 16; ++nn) {
                uint32_t bf[2];
                bf[0] = __float_as_uint(Vs[(kk + t4) * ASTRIDE + nn * 8 + g]);
                bf[1] = __float_as_uint(Vs[(kk + t4 + 4) * ASTRIDE + nn * 8 + g]);
                mma8(o[nn], af, bf);
            }
        }
    }

    // ---- normalize and write
    float inv0 = 1.f / l0, inv1 = 1.f / l1;
#pragma unroll
    for (int nn = 0; nn < 16; ++nn) {
        int c = h * HD + nn * 8 + (t4 << 1);
        float2 v;
        v.x = o[nn][0] * inv0; v.y = o[nn][1] * inv0;
        *reinterpret_cast<float2*>(Oa + (size_t)r0g * DM + c) = v;
        v.x = o[nn][2] * inv1; v.y = o[nn][3] * inv1;
        *reinterpret_cast<float2*>(Oa + (size_t)(r0g + 8) * DM + c) = v;
    }
}

extern "C" void kernel_launch(void* const* d_in, const int* in_sizes, int n_in,
                              void* d_out, int out_size)
{
    (void)in_sizes; (void)n_in; (void)out_size;
    const float* x  = (const float*)d_in[0];
    const float* wq = (const float*)d_in[1];
    const float* wk = (const float*)d_in[2];
    const float* wv = (const float*)d_in[3];
    const float* wo = (const float*)d_in[4];
    const float* fc = (const float*)d_in[5];
    const float* fs = (const float*)d_in[6];
    // d_in[7] (mask) handled analytically as causal; d_in[8] (start_pos) == 0.
    float* out = (float*)d_out;

    float *q, *k, *v, *att;
    cudaGetSymbolAddress((void**)&q,   g_q);
    cudaGetSymbolAddress((void**)&k,   g_k);
    cudaGetSymbolAddress((void**)&v,   g_v);
    cudaGetSymbolAddress((void**)&att, g_att);

    cudaFuncSetAttribute(attn_fused,
                         cudaFuncAttributeMaxDynamicSharedMemorySize, ATN_SMEM);

    const dim3 blk(256);
    const dim3 gproj(DM / 128, SQ / 128, 1);

    // Projections (RoPE fused into Q/K epilogues)
    gemm_tf32<true ><<<gproj, blk>>>(x, wq, q, DM, DM, DM, DM, 1.f, fc, fs);
    gemm_tf32<true ><<<gproj, blk>>>(x, wk, k, DM, DM, DM, DM, 1.f, fc, fs);
    gemm_tf32<false><<<gproj, blk>>>(x, wv, v, DM, DM, DM, DM, 1.f, nullptr, nullptr);

    // Fused causal attention
    attn_fused<<<dim3(SQ / 128, NH), blk, ATN_SMEM>>>(q, k, v, att);

    // Output projection
    gemm_tf32<false><<<gproj, blk>>>(att, wo, out, DM, DM, DM, DM, 1.f, nullptr, nullptr);
}

// round 11
// speedup vs baseline: 1.2301x; 1.2301x over previous
#include <cuda_runtime.h>
#include <cstdint>

#define SQ 2048
#define DM 4096
#define NH 32
#define HD 128

// Scratch (allocation-free rule: __device__ globals). 4 x 32 MB.
__device__ float g_q[(size_t)SQ * DM];
__device__ float g_k[(size_t)SQ * DM];
__device__ float g_v[(size_t)SQ * DM];
__device__ float g_att[(size_t)SQ * DM];

// ============================================================================
// Helpers (baseline PTX only — no sm_103a-gated instructions)
// ============================================================================
__device__ __forceinline__ float to_tf32(float x) {
    uint32_t u;
    asm("cvt.rna.tf32.f32 %0, %1;" : "=r"(u) : "f"(x));
    return __uint_as_float(u);
}

__device__ __forceinline__ uint32_t tf32u(float x) {
    uint32_t u;
    asm("cvt.rna.tf32.f32 %0, %1;" : "=r"(u) : "f"(x));
    return u;
}

__device__ __forceinline__ uint32_t smem_u32(const void* p) {
    uint32_t a;
    asm("{ .reg .u64 t; cvta.to.shared.u64 t, %1; cvt.u32.u64 %0, t; }"
        : "=r"(a) : "l"(p));
    return a;
}

__device__ __forceinline__ void cp16(uint32_t dst, const void* src) {
    asm volatile(
        "{ .reg .u64 gp; cvta.to.global.u64 gp, %1;"
        "  cp.async.cg.shared.global [%0], [gp], 16; }"
        :: "r"(dst), "l"(src) : "memory");
}
#define CP_COMMIT() asm volatile("cp.async.commit_group;" ::: "memory")
#define CP_WAIT2()  asm volatile("cp.async.wait_group 2;" ::: "memory")

__device__ __forceinline__ void mma8(float* d, const uint32_t* a, const uint32_t* b) {
    asm volatile(
        "mma.sync.aligned.m16n8k8.row.col.f32.tf32.tf32.f32 "
        "{%0,%1,%2,%3}, {%4,%5,%6,%7}, {%8,%9}, {%0,%1,%2,%3};"
        : "+f"(d[0]), "+f"(d[1]), "+f"(d[2]), "+f"(d[3])
        : "r"(a[0]), "r"(a[1]), "r"(a[2]), "r"(a[3]), "r"(b[0]), "r"(b[1]));
}

// ============================================================================
// Pipelined TF32 GEMM: C[2048,4096] = A[2048,4096] @ B[4096,4096], row-major.
// CTA tile 128x128, K-stage 32, 3-stage cp.async pipeline, 256 threads,
// 2 CTAs/SM. A staged [m][k] (stride 36 -> conflict-free A-frag LDS),
// B staged [k][n] (stride 132 -> <=2-way). tf32 cvt at fragment load.
// ROPE=true fuses rotary embedding into the epilogue.
// ============================================================================
#define NSTAGE 3
#define AST 36                       // A row stride (floats), 144 B
#define BST 132                      // B row stride (floats), 528 B
#define ATILE (128 * AST)            // 4608 floats
#define BTILE (32 * BST)             // 4224 floats
#define STAGEF (ATILE + BTILE)       // 8832 floats
#define GEMM_DSMEM (NSTAGE * STAGEF * 4)   // 105984 B
#define GNIT (DM / 32)               // 128 k-iterations

template <bool ROPE>
__global__ void __launch_bounds__(256, 2) gemm_mm(
    const float* __restrict__ A, const float* __restrict__ B, float* __restrict__ C,
    const float* __restrict__ fc, const float* __restrict__ fs)
{
    extern __shared__ float sm[];
    const uint32_t smb = smem_u32(sm);

    const int tid  = threadIdx.x;
    const int lane = tid & 31;
    const int warp = tid >> 5;
    const int bm = blockIdx.y * 128;
    const int bn = blockIdx.x * 128;
    const int wm = (warp & 3) * 32;     // 4 warps along M
    const int wn = (warp >> 2) * 64;    // 2 warps along N
    const int g  = lane >> 2;
    const int t4 = lane & 3;

    // staging jobs: 4 x 16B for A (128x32) and 4 x 16B for B (32x128) per thread
    int arow[4], akq[4], brow[4], bcol[4];
#pragma unroll
    for (int it = 0; it < 4; ++it) {
        int f = tid + it * 256;
        arow[it] = f >> 3;  akq[it]  = (f & 7) << 2;
        brow[it] = f >> 5;  bcol[it] = (f & 31) << 2;
    }

    float acc[2][8][4];
#pragma unroll
    for (int a = 0; a < 2; a++)
#pragma unroll
        for (int b = 0; b < 8; b++)
#pragma unroll
            for (int c = 0; c < 4; c++) acc[a][b][c] = 0.f;

    // ---- prologue: stages 0 and 1 in flight
#pragma unroll
    for (int p = 0; p < 2; ++p) {
        uint32_t sa = smb + (uint32_t)(p * STAGEF) * 4;
        uint32_t sb = sa + ATILE * 4;
        int k0 = p * 32;
#pragma unroll
        for (int it = 0; it < 4; ++it) {
            cp16(sa + (uint32_t)(arow[it] * AST + akq[it]) * 4,
                 A + (size_t)(bm + arow[it]) * DM + k0 + akq[it]);
            cp16(sb + (uint32_t)(brow[it] * BST + bcol[it]) * 4,
                 B + (size_t)(k0 + brow[it]) * DM + bn + bcol[it]);
        }
        CP_COMMIT();
    }

    for (int i = 0; i < GNIT; ++i) {
        // ---- issue stage i+2 (or an empty group to keep the count in step)
        if (i + 2 < GNIT) {
            int st = (i + 2) % NSTAGE;
            uint32_t sa = smb + (uint32_t)(st * STAGEF) * 4;
            uint32_t sb = sa + ATILE * 4;
            int k0 = (i + 2) * 32;
#pragma unroll
            for (int it = 0; it < 4; ++it) {
                cp16(sa + (uint32_t)(arow[it] * AST + akq[it]) * 4,
                     A + (size_t)(bm + arow[it]) * DM + k0 + akq[it]);
                cp16(sb + (uint32_t)(brow[it] * BST + bcol[it]) * 4,
                     B + (size_t)(k0 + brow[it]) * DM + bn + bcol[it]);
            }
        }
        CP_COMMIT();

        CP_WAIT2();            // stage i resident (this thread's copies)
        __syncthreads();       // ... and everyone else's

        const float* sa = sm + (i % NSTAGE) * STAGEF;
        const float* sb = sa + ATILE;

#pragma unroll
        for (int kk = 0; kk < 32; kk += 8) {
            uint32_t af[2][4], bf[8][2];
#pragma unroll
            for (int mt = 0; mt < 2; ++mt) {
                int r = wm + mt * 16 + g;
                af[mt][0] = tf32u(sa[r * AST + kk + t4]);
                af[mt][1] = tf32u(sa[(r + 8) * AST + kk + t4]);
                af[mt][2] = tf32u(sa[r * AST + kk + t4 + 4]);
                af[mt][3] = tf32u(sa[(r + 8) * AST + kk + t4 + 4]);
            }
#pragma unroll
            for (int nt = 0; nt < 8; ++nt) {
                int c = wn + nt * 8 + g;
                bf[nt][0] = tf32u(sb[(kk + t4) * BST + c]);
                bf[nt][1] = tf32u(sb[(kk + t4 + 4) * BST + c]);
            }
#pragma unroll
            for (int mt = 0; mt < 2; ++mt)
#pragma unroll
                for (int nt = 0; nt < 8; ++nt)
                    mma8(acc[mt][nt], af[mt], bf[nt]);
        }
        __syncthreads();       // stage i fully consumed; safe to clobber next iter
    }

    // ---- epilogue (optionally fused RoPE: adjacent cols == (c0,c1)/(c2,c3))
#pragma unroll
    for (int mt = 0; mt < 2; ++mt)
#pragma unroll
        for (int nt = 0; nt < 8; ++nt) {
            int r = bm + wm + mt * 16 + g;
            int c = bn + wn + nt * 8 + (t4 << 1);
            float x0 = acc[mt][nt][0];
            float x1 = acc[mt][nt][1];
            float x2 = acc[mt][nt][2];
            float x3 = acc[mt][nt][3];
            if (ROPE) {
                int fi = (c & (HD - 1)) >> 1;
                float c0 = fc[(size_t)r * (HD / 2) + fi];
                float s0 = fs[(size_t)r * (HD / 2) + fi];
                float c1 = fc[(size_t)(r + 8) * (HD / 2) + fi];
                float s1 = fs[(size_t)(r + 8) * (HD / 2) + fi];
                float y0 = x0 * c0 - x1 * s0;
                float y1 = x0 * s0 + x1 * c0;
                float y2 = x2 * c1 - x3 * s1;
                float y3 = x2 * s1 + x3 * c1;
                x0 = y0; x1 = y1; x2 = y2; x3 = y3;
            }
            float2 v;
            v.x = x0; v.y = x1;
            *reinterpret_cast<float2*>(C + (size_t)r * DM + c) = v;
            v.x = x2; v.y = x3;
            *reinterpret_cast<float2*>(C + (size_t)(r + 8) * DM + c) = v;
        }
}

// ============================================================================
// Fused flash attention (causal), tf32 mma.sync (unchanged, known-good).
// ============================================================================
#define ASTRIDE 136
#define ATN_SMEM (3 * 128 * ASTRIDE * (int)sizeof(float))

__global__ void __launch_bounds__(256, 1) attn_fused(
    const float* __restrict__ Q, const float* __restrict__ K,
    const float* __restrict__ V, float* __restrict__ Oa)
{
    extern __shared__ float smem[];
    float* Qs = smem;                      // [d][q]
    float* Ks = smem + 128 * ASTRIDE;      // [d][j]
    float* Vs = smem + 2 * 128 * ASTRIDE;  // [j][d]

    const int h  = blockIdx.y;
    const int i0 = (SQ / 128 - 1 - (int)blockIdx.x) * 128;  // heavy tiles first
    const int tid  = threadIdx.x;
    const int lane = tid & 31;
    const int warp = tid >> 5;
    const int g  = lane >> 2;
    const int t4 = lane & 3;
    const int w16 = warp * 16;
    const float scale = 0.08838834764831845f;   // 1/sqrt(128)

#pragma unroll
    for (int it = 0; it < 16; ++it) {
        int f   = tid + it * 256;
        int row = f >> 5;
        int c4  = (f & 31) << 2;
        float4 v4 = *reinterpret_cast<const float4*>(
            Q + (size_t)(i0 + row) * DM + h * HD + c4);
        Qs[(c4 + 0) * ASTRIDE + row] = to_tf32(v4.x);
        Qs[(c4 + 1) * ASTRIDE + row] = to_tf32(v4.y);
        Qs[(c4 + 2) * ASTRIDE + row] = to_tf32(v4.z);
        Qs[(c4 + 3) * ASTRIDE + row] = to_tf32(v4.w);
    }

    float o[16][4];
#pragma unroll
    for (int n = 0; n < 16; ++n)
#pragma unroll
        for (int c = 0; c < 4; ++c) o[n][c] = 0.f;
    float m0 = -1e30f, m1 = -1e30f, l0 = 0.f, l1 = 0.f;

    const int r0g = i0 + w16 + g;
    const unsigned FULL = 0xffffffffu;

    for (int j0 = 0; j0 <= i0; j0 += 128) {
        __syncthreads();
#pragma unroll
        for (int it = 0; it < 16; ++it) {
            int f   = tid + it * 256;
            int row = f >> 5;
            int c4  = (f & 31) << 2;
            float4 kv = *reinterpret_cast<const float4*>(
                K + (size_t)(j0 + row) * DM + h * HD + c4);
            Ks[(c4 + 0) * ASTRIDE + row] = to_tf32(kv.x);
            Ks[(c4 + 1) * ASTRIDE + row] = to_tf32(kv.y);
            Ks[(c4 + 2) * ASTRIDE + row] = to_tf32(kv.z);
            Ks[(c4 + 3) * ASTRIDE + row] = to_tf32(kv.w);
            float4 vv = *reinterpret_cast<const float4*>(
                V + (size_t)(j0 + row) * DM + h * HD + c4);
            float4 w4;
            w4.x = to_tf32(vv.x); w4.y = to_tf32(vv.y);
            w4.z = to_tf32(vv.z); w4.w = to_tf32(vv.w);
            *reinterpret_cast<float4*>(&Vs[row * ASTRIDE + c4]) = w4;
        }
        __syncthreads();

        float s[16][4];
#pragma unroll
        for (int n = 0; n < 16; ++n)
#pragma unroll
            for (int c = 0; c < 4; ++c) s[n][c] = 0.f;

#pragma unroll
        for (int kk = 0; kk < 128; kk += 8) {
            uint32_t af[4];
            af[0] = __float_as_uint(Qs[(kk + t4) * ASTRIDE + w16 + g]);
            af[1] = __float_as_uint(Qs[(kk + t4) * ASTRIDE + w16 + g + 8]);
            af[2] = __float_as_uint(Qs[(kk + t4 + 4) * ASTRIDE + w16 + g]);
            af[3] = __float_as_uint(Qs[(kk + t4 + 4) * ASTRIDE + w16 + g + 8]);
#pragma unroll
            for (int n = 0; n < 16; ++n) {
                uint32_t bf[2];
                bf[0] = __float_as_uint(Ks[(kk + t4) * ASTRIDE + n * 8 + g]);
                bf[1] = __float_as_uint(Ks[(kk + t4 + 4) * ASTRIDE + n * 8 + g]);
                mma8(s[n], af, bf);
            }
        }

        const bool diag = (j0 == i0);
#pragma unroll
        for (int n = 0; n < 16; ++n) {
            int c = j0 + n * 8 + (t4 << 1);
            s[n][0] *= scale; s[n][1] *= scale;
            s[n][2] *= scale; s[n][3] *= scale;
            if (diag) {
                if (c     > r0g)     s[n][0] = -1e30f;
                if (c + 1 > r0g)     s[n][1] = -1e30f;
                if (c     > r0g + 8) s[n][2] = -1e30f;
                if (c + 1 > r0g + 8) s[n][3] = -1e30f;
            }
        }

        float tm0 = -1e30f, tm1 = -1e30f;
#pragma unroll
        for (int n = 0; n < 16; ++n) {
            tm0 = fmaxf(tm0, fmaxf(s[n][0], s[n][1]));
            tm1 = fmaxf(tm1, fmaxf(s[n][2], s[n][3]));
        }
        tm0 = fmaxf(tm0, __shfl_xor_sync(FULL, tm0, 1));
        tm0 = fmaxf(tm0, __shfl_xor_sync(FULL, tm0, 2));
        tm1 = fmaxf(tm1, __shfl_xor_sync(FULL, tm1, 1));
        tm1 = fmaxf(tm1, __shfl_xor_sync(FULL, tm1, 2));
        float nm0 = fmaxf(m0, tm0), nm1 = fmaxf(m1, tm1);
        float a0 = __expf(m0 - nm0), a1 = __expf(m1 - nm1);
        m0 = nm0; m1 = nm1;

        float ts0 = 0.f, ts1 = 0.f;
#pragma unroll
        for (int n = 0; n < 16; ++n) {
            s[n][0] = __expf(s[n][0] - m0);
            s[n][1] = __expf(s[n][1] - m0);
            s[n][2] = __expf(s[n][2] - m1);
            s[n][3] = __expf(s[n][3] - m1);
            ts0 += s[n][0] + s[n][1];
            ts1 += s[n][2] + s[n][3];
        }
        ts0 += __shfl_xor_sync(FULL, ts0, 1);
        ts0 += __shfl_xor_sync(FULL, ts0, 2);
        ts1 += __shfl_xor_sync(FULL, ts1, 1);
        ts1 += __shfl_xor_sync(FULL, ts1, 2);
        l0 = l0 * a0 + ts0;
        l1 = l1 * a1 + ts1;
#pragma unroll
        for (int n = 0; n < 16; ++n) {
            o[n][0] *= a0; o[n][1] *= a0;
            o[n][2] *= a1; o[n][3] *= a1;
        }

        const int bse = lane & 28;
        const int sl0 = bse + (t4 >> 1);
        const int sl1 = sl0 + 2;
        const bool odd = (t4 & 1);
#pragma unroll
        for (int n = 0; n < 16; ++n) {
            float pa = __shfl_sync(FULL, s[n][0], sl0);
            float pb = __shfl_sync(FULL, s[n][1], sl0);
            float pc = __shfl_sync(FULL, s[n][2], sl0);
            float pd = __shfl_sync(FULL, s[n][3], sl0);
            float pe = __shfl_sync(FULL, s[n][0], sl1);
            float pf = __shfl_sync(FULL, s[n][1], sl1);
            float pg = __shfl_sync(FULL, s[n][2], sl1);
            float ph = __shfl_sync(FULL, s[n][3], sl1);
            uint32_t af[4];
            af[0] = __float_as_uint(to_tf32(odd ? pb : pa));
            af[1] = __float_as_uint(to_tf32(odd ? pd : pc));
            af[2] = __float_as_uint(to_tf32(odd ? pf : pe));
            af[3] = __float_as_uint(to_tf32(odd ? ph : pg));
            int kk = n * 8;
#pragma unroll
            for (int nn = 0; nn < 16; ++nn) {
                uint32_t bf[2];
                bf[0] = __float_as_uint(Vs[(kk + t4) * ASTRIDE + nn * 8 + g]);
                bf[1] = __float_as_uint(Vs[(kk + t4 + 4) * ASTRIDE + nn * 8 + g]);
                mma8(o[nn], af, bf);
            }
        }
    }

    float inv0 = 1.f / l0, inv1 = 1.f / l1;
#pragma unroll
    for (int nn = 0; nn < 16; ++nn) {
        int c = h * HD + nn * 8 + (t4 << 1);
        float2 v;
        v.x = o[nn][0] * inv0; v.y = o[nn][1] * inv0;
        *reinterpret_cast<float2*>(Oa + (size_t)r0g * DM + c) = v;
        v.x = o[nn][2] * inv1; v.y = o[nn][3] * inv1;
        *reinterpret_cast<float2*>(Oa + (size_t)(r0g + 8) * DM + c) = v;
    }
}

extern "C" void kernel_launch(void* const* d_in, const int* in_sizes, int n_in,
                              void* d_out, int out_size)
{
    (void)in_sizes; (void)n_in; (void)out_size;
    const float* x  = (const float*)d_in[0];
    const float* wq = (const float*)d_in[1];
    const float* wk = (const float*)d_in[2];
    const float* wv = (const float*)d_in[3];
    const float* wo = (const float*)d_in[4];
    const float* fc = (const float*)d_in[5];
    const float* fs = (const float*)d_in[6];
    // d_in[7] (mask) handled analytically as causal; d_in[8] (start_pos) == 0.
    float* out = (float*)d_out;

    float *q, *k, *v, *att;
    cudaGetSymbolAddress((void**)&q,   g_q);
    cudaGetSymbolAddress((void**)&k,   g_k);
    cudaGetSymbolAddress((void**)&v,   g_v);
    cudaGetSymbolAddress((void**)&att, g_att);

    cudaFuncSetAttribute(gemm_mm<true>,
                         cudaFuncAttributeMaxDynamicSharedMemorySize, GEMM_DSMEM);
    cudaFuncSetAttribute(gemm_mm<false>,
                         cudaFuncAttributeMaxDynamicSharedMemorySize, GEMM_DSMEM);
    cudaFuncSetAttribute(attn_fused,
                         cudaFuncAttributeMaxDynamicSharedMemorySize, ATN_SMEM);

    const dim3 blk(256);
    const dim3 gproj(DM / 128, SQ / 128, 1);   // (32, 16)

    // Projections (RoPE fused into Q/K epilogues)
    gemm_mm<true ><<<gproj, blk, GEMM_DSMEM>>>(x, wq, q, fc, fs);
    gemm_mm<true ><<<gproj, blk, GEMM_DSMEM>>>(x, wk, k, fc, fs);
    gemm_mm<false><<<gproj, blk, GEMM_DSMEM>>>(x, wv, v, nullptr, nullptr);

    // Fused causal attention
    attn_fused<<<dim3(SQ / 128, NH), blk, ATN_SMEM>>>(q, k, v, att);

    // Output projection
    gemm_mm<false><<<gproj, blk, GEMM_DSMEM>>>(att, wo, out, nullptr, nullptr);
}

// round 12
// speedup vs baseline: 1.5429x; 1.2542x over previous
#include <cuda_runtime.h>
#include <cstdint>

#define SQ 2048
#define DM 4096
#define NH 32
#define HD 128

// Scratch (allocation-free rule: __device__ globals).
__device__ float g_q[(size_t)SQ * DM];
__device__ float g_k[(size_t)SQ * DM];
__device__ float g_v[(size_t)SQ * DM];
__device__ float g_att[(size_t)SQ * DM];
__device__ float g_xc[(size_t)SQ * DM];     // tf32(x)
__device__ float g_wt[(size_t)DM * DM];     // tf32(w^T), reused serially

// ============================================================================
// Helpers (baseline PTX only — harness compiles at plain sm_103)
// ============================================================================
__device__ __forceinline__ float to_tf32(float x) {
    uint32_t u;
    asm("cvt.rna.tf32.f32 %0, %1;" : "=r"(u) : "f"(x));
    return __uint_as_float(u);
}

__device__ __forceinline__ uint32_t smem_u32(const void* p) {
    uint32_t a;
    asm("{ .reg .u64 t; cvta.to.shared.u64 t, %1; cvt.u32.u64 %0, t; }"
        : "=r"(a) : "l"(p));
    return a;
}

__device__ __forceinline__ void cp16(uint32_t dst, const void* src) {
    asm volatile(
        "{ .reg .u64 gp; cvta.to.global.u64 gp, %1;"
        "  cp.async.cg.shared.global [%0], [gp], 16; }"
        :: "r"(dst), "l"(src) : "memory");
}
#define CP_COMMIT() asm volatile("cp.async.commit_group;" ::: "memory")
#define CP_WAIT2()  asm volatile("cp.async.wait_group 2;" ::: "memory")

// ldmatrix x4 on tf32 data: four 8x4 b32 matrices; reg r of thread t holds
// element (t/4, t%4) of matrix r; matrix r's rows are addressed by threads 8r..8r+7.
__device__ __forceinline__ void ldsm4(uint32_t* r, uint32_t addr) {
    asm volatile("ldmatrix.sync.aligned.m8n8.x4.shared.b16 {%0,%1,%2,%3}, [%4];"
        : "=r"(r[0]), "=r"(r[1]), "=r"(r[2]), "=r"(r[3]) : "r"(addr));
}

__device__ __forceinline__ void mma8(float* d, const uint32_t* a, const uint32_t* b) {
    asm volatile(
        "mma.sync.aligned.m16n8k8.row.col.f32.tf32.tf32.f32 "
        "{%0,%1,%2,%3}, {%4,%5,%6,%7}, {%8,%9}, {%0,%1,%2,%3};"
        : "+f"(d[0]), "+f"(d[1]), "+f"(d[2]), "+f"(d[3])
        : "r"(a[0]), "r"(a[1]), "r"(a[2]), "r"(a[3]), "r"(b[0]), "r"(b[1]));
}

// ============================================================================
// Pre-pass kernels
// ============================================================================
__global__ void conv_tf32(const float4* __restrict__ s, float4* __restrict__ d) {
    int i = blockIdx.x * blockDim.x + threadIdx.x;
    float4 v = s[i];
    v.x = to_tf32(v.x); v.y = to_tf32(v.y);
    v.z = to_tf32(v.z); v.w = to_tf32(v.w);
    d[i] = v;
}

// dst[n][k] = tf32(src[k][n]), DM x DM
__global__ void transpose_tf32(const float* __restrict__ src, float* __restrict__ dst) {
    __shared__ float t[32][33];
    int x  = blockIdx.x * 32 + threadIdx.x;   // n in src
    int y0 = blockIdx.y * 32;                 // k base
#pragma unroll
    for (int i = 0; i < 32; i += 8)
        t[threadIdx.y + i][threadIdx.x] =
            to_tf32(src[(size_t)(y0 + threadIdx.y + i) * DM + x]);
    __syncthreads();
    int xo = blockIdx.y * 32 + threadIdx.x;   // k in dst
    int yo = blockIdx.x * 32;                 // n base
#pragma unroll
    for (int i = 0; i < 32; i += 8)
        dst[(size_t)(yo + threadIdx.y + i) * DM + xo] = t[threadIdx.x][threadIdx.y + i];
}

// ============================================================================
// TF32 GEMM via ldmatrix: C[2048,4096] = A[2048,4096] @ Bt^T, A and Bt both
// row-major [row][k], pre-converted to tf32. CTA tile 128x128, K-stage 32,
// 3-stage cp.async, 2 CTAs/SM. Row stride 36 floats (144 B): cp.async staging
// at the 4-cyc crossbar floor, ldmatrix reads conflict-free.
// ============================================================================
#define NSTAGE 3
#define RST 36
#define TILEB (128 * RST * 4)               // 18432 B per operand tile
#define STAGEB (2 * TILEB)                  // 36864 B
#define GEMM_DSMEM (NSTAGE * STAGEB)        // 110592 B
#define GNIT (DM / 32)                      // 128

template <bool ROPE, bool OTF32>
__global__ void __launch_bounds__(256, 2) gemm_lm(
    const float* __restrict__ A, const float* __restrict__ Bt, float* __restrict__ C,
    const float* __restrict__ fc, const float* __restrict__ fs)
{
    extern __shared__ float sm[];
    const uint32_t smb = smem_u32(sm);

    const int tid  = threadIdx.x;
    const int lane = tid & 31;
    const int warp = tid >> 5;
    const int bm = blockIdx.y * 128;
    const int bn = blockIdx.x * 128;
    const int wm = (warp & 3) * 32;     // 4 warps along M
    const int wn = (warp >> 2) * 64;    // 2 warps along N
    const int g  = lane >> 2;
    const int t4 = lane & 3;

    // staging jobs: 4 x 16B for each operand per thread per stage
    int row[4], chk[4];
#pragma unroll
    for (int it = 0; it < 4; ++it) {
        int f = tid + it * 256;
        row[it] = f >> 3;
        chk[it] = f & 7;
    }

    // ldmatrix per-thread source rows/cols
    // A x4: m0=rows lo/k lo, m1=rows hi/k lo, m2=lo/k hi, m3=hi/k hi
    const int arow = ((lane >> 3) & 1) * 8 + (lane & 7);
    const uint32_t acol16 = ((lane >> 4) & 1) * 16;
    const uint32_t abase = (uint32_t)(wm + arow) * 144 + acol16;
    // B x4: m0=blk0/k lo, m1=blk0/k hi, m2=blk1/k lo, m3=blk1/k hi
    const int brow = ((lane >> 4) & 1) * 8 + (lane & 7);
    const uint32_t bcol16 = ((lane >> 3) & 1) * 16;
    const uint32_t bbase = (uint32_t)(wn + brow) * 144 + bcol16;

    float acc[2][8][4];
#pragma unroll
    for (int a = 0; a < 2; a++)
#pragma unroll
        for (int b = 0; b < 8; b++)
#pragma unroll
            for (int c = 0; c < 4; c++) acc[a][b][c] = 0.f;

    // ---- prologue: stages 0,1 in flight
#pragma unroll
    for (int p = 0; p < 2; ++p) {
        uint32_t sa = smb + (uint32_t)(p * STAGEB);
        int k0 = p * 32;
#pragma unroll
        for (int it = 0; it < 4; ++it) {
            uint32_t doff = (uint32_t)(row[it] * 144 + chk[it] * 16);
            cp16(sa + doff,         A  + (size_t)(bm + row[it]) * DM + k0 + chk[it] * 4);
            cp16(sa + TILEB + doff, Bt + (size_t)(bn + row[it]) * DM + k0 + chk[it] * 4);
        }
        CP_COMMIT();
    }

    for (int i = 0; i < GNIT; ++i) {
        if (i + 2 < GNIT) {
            uint32_t sa = smb + (uint32_t)(((i + 2) % NSTAGE) * STAGEB);
            int k0 = (i + 2) * 32;
#pragma unroll
            for (int it = 0; it < 4; ++it) {
                uint32_t doff = (uint32_t)(row[it] * 144 + chk[it] * 16);
                cp16(sa + doff,         A  + (size_t)(bm + row[it]) * DM + k0 + chk[it] * 4);
                cp16(sa + TILEB + doff, Bt + (size_t)(bn + row[it]) * DM + k0 + chk[it] * 4);
            }
        }
        CP_COMMIT();
        CP_WAIT2();
        __syncthreads();

        const uint32_t sa = smb + (uint32_t)((i % NSTAGE) * STAGEB);
        const uint32_t sb = sa + TILEB;

#pragma unroll
        for (int kk = 0; kk < 32; kk += 8) {
            uint32_t af[2][4];
            ldsm4(af[0], sa + abase + kk * 4);
            ldsm4(af[1], sa + abase + 16 * 144 + kk * 4);
            uint32_t bq[4][4];
#pragma unroll
            for (int p = 0; p < 4; ++p)
                ldsm4(bq[p], sb + bbase + (uint32_t)(p * 16 * 144) + kk * 4);
#pragma unroll
            for (int mt = 0; mt < 2; ++mt)
#pragma unroll
                for (int nt = 0; nt < 8; ++nt)
                    mma8(acc[mt][nt], af[mt], &bq[nt >> 1][(nt & 1) * 2]);
        }
        __syncthreads();
    }

    // ---- epilogue (optional fused RoPE; optional tf32-rounded output)
#pragma unroll
    for (int mt = 0; mt < 2; ++mt)
#pragma unroll
        for (int nt = 0; nt < 8; ++nt) {
            int r = bm + wm + mt * 16 + g;
            int c = bn + wn + nt * 8 + (t4 << 1);
            float x0 = acc[mt][nt][0];
            float x1 = acc[mt][nt][1];
            float x2 = acc[mt][nt][2];
            float x3 = acc[mt][nt][3];
            if (ROPE) {
                int fi = (c & (HD - 1)) >> 1;
                float c0 = fc[(size_t)r * (HD / 2) + fi];
                float s0 = fs[(size_t)r * (HD / 2) + fi];
                float c1 = fc[(size_t)(r + 8) * (HD / 2) + fi];
                float s1 = fs[(size_t)(r + 8) * (HD / 2) + fi];
                float y0 = x0 * c0 - x1 * s0;
                float y1 = x0 * s0 + x1 * c0;
                float y2 = x2 * c1 - x3 * s1;
                float y3 = x2 * s1 + x3 * c1;
                x0 = y0; x1 = y1; x2 = y2; x3 = y3;
            }
            if (OTF32) {
                x0 = to_tf32(x0); x1 = to_tf32(x1);
                x2 = to_tf32(x2); x3 = to_tf32(x3);
            }
            float2 v;
            v.x = x0; v.y = x1;
            *reinterpret_cast<float2*>(C + (size_t)r * DM + c) = v;
            v.x = x2; v.y = x3;
            *reinterpret_cast<float2*>(C + (size_t)(r + 8) * DM + c) = v;
        }
}

// ============================================================================
// Fused flash attention (causal), tf32 mma.sync.
// Inputs q,k,v are already tf32-rounded (gemm epilogues) -> no cvt at staging.
// Q,K staged natural [row][d] stride 132 (ldmatrix-friendly, conflict-free);
// V staged natural [j][d] stride 136 (scalar-LDS conflict-free, proven).
// QK fragments via ldmatrix; PV path unchanged.
// ============================================================================
#define QST 132
#define VST 136
#define QS_OFF 0
#define KS_OFF (128 * QST)
#define VS_OFF (KS_OFF + 128 * QST)
#define ATN_SMEM ((VS_OFF + 128 * VST) * (int)sizeof(float))   // 204800 B

__global__ void __launch_bounds__(256, 1) attn_fused(
    const float* __restrict__ Q, const float* __restrict__ K,
    const float* __restrict__ V, float* __restrict__ Oa)
{
    extern __shared__ float smem[];
    const uint32_t smb = smem_u32(smem);

    const int h  = blockIdx.y;
    const int i0 = (SQ / 128 - 1 - (int)blockIdx.x) * 128;  // heavy tiles first
    const int tid  = threadIdx.x;
    const int lane = tid & 31;
    const int warp = tid >> 5;
    const int g  = lane >> 2;
    const int t4 = lane & 3;
    const int w16 = warp * 16;
    const float scale = 0.08838834764831845f;   // 1/sqrt(128)

    // ldmatrix address bases
    const int qrow = ((lane >> 3) & 1) * 8 + (lane & 7);
    const uint32_t qaddr = smb + (uint32_t)(QS_OFF + (w16 + qrow) * QST) * 4
                         + ((lane >> 4) & 1) * 16;
    const int krow = ((lane >> 4) & 1) * 8 + (lane & 7);
    const uint32_t kaddr = smb + (uint32_t)(KS_OFF + krow * QST) * 4
                         + ((lane >> 3) & 1) * 16;

    // ---- load Q tile once (natural layout, STS.128)
#pragma unroll
    for (int it = 0; it < 16; ++it) {
        int f   = tid + it * 256;
        int r   = f >> 5;
        int c4  = (f & 31) << 2;
        float4 v4 = *reinterpret_cast<const float4*>(
            Q + (size_t)(i0 + r) * DM + h * HD + c4);
        *reinterpret_cast<float4*>(&smem[QS_OFF + r * QST + c4]) = v4;
    }

    float o[16][4];
#pragma unroll
    for (int n = 0; n < 16; ++n)
#pragma unroll
        for (int c = 0; c < 4; ++c) o[n][c] = 0.f;
    float m0 = -1e30f, m1 = -1e30f, l0 = 0.f, l1 = 0.f;

    const int r0g = i0 + w16 + g;
    const unsigned FULL = 0xffffffffu;

    for (int j0 = 0; j0 <= i0; j0 += 128) {
        __syncthreads();   // previous iteration's smem reads done (covers Q load too)
#pragma unroll
        for (int it = 0; it < 16; ++it) {
            int f   = tid + it * 256;
            int r   = f >> 5;
            int c4  = (f & 31) << 2;
            float4 kv = *reinterpret_cast<const float4*>(
                K + (size_t)(j0 + r) * DM + h * HD + c4);
            *reinterpret_cast<float4*>(&smem[KS_OFF + r * QST + c4]) = kv;
            float4 vv = *reinterpret_cast<const float4*>(
                V + (size_t)(j0 + r) * DM + h * HD + c4);
            *reinterpret_cast<float4*>(&smem[VS_OFF + r * VST + c4]) = vv;
        }
        __syncthreads();

        // ---- S = Q @ K^T via ldmatrix fragments
        float s[16][4];
#pragma unroll
        for (int n = 0; n < 16; ++n)
#pragma unroll
            for (int c = 0; c < 4; ++c) s[n][c] = 0.f;

#pragma unroll
        for (int kk = 0; kk < 128; kk += 8) {
            uint32_t af[4];
            ldsm4(af, qaddr + kk * 4);
            uint32_t bq[8][4];
#pragma unroll
            for (int p = 0; p < 8; ++p)
                ldsm4(bq[p], kaddr + (uint32_t)(p * 16 * QST) * 4 + kk * 4);
#pragma unroll
            for (int n = 0; n < 16; ++n)
                mma8(s[n], af, &bq[n >> 1][(n & 1) * 2]);
        }

        // ---- scale + causal mask (diagonal tile only)
        const bool diag = (j0 == i0);
#pragma unroll
        for (int n = 0; n < 16; ++n) {
            int c = j0 + n * 8 + (t4 << 1);
            s[n][0] *= scale; s[n][1] *= scale;
            s[n][2] *= scale; s[n][3] *= scale;
            if (diag) {
                if (c     > r0g)     s[n][0] = -1e30f;
                if (c + 1 > r0g)     s[n][1] = -1e30f;
                if (c     > r0g + 8) s[n][2] = -1e30f;
                if (c + 1 > r0g + 8) s[n][3] = -1e30f;
            }
        }

        // ---- online softmax
        float tm0 = -1e30f, tm1 = -1e30f;
#pragma unroll
        for (int n = 0; n < 16; ++n) {
            tm0 = fmaxf(tm0, fmaxf(s[n][0], s[n][1]));
            tm1 = fmaxf(tm1, fmaxf(s[n][2], s[n][3]));
        }
        tm0 = fmaxf(tm0, __shfl_xor_sync(FULL, tm0, 1));
        tm0 = fmaxf(tm0, __shfl_xor_sync(FULL, tm0, 2));
        tm1 = fmaxf(tm1, __shfl_xor_sync(FULL, tm1, 1));
        tm1 = fmaxf(tm1, __shfl_xor_sync(FULL, tm1, 2));
        float nm0 = fmaxf(m0, tm0), nm1 = fmaxf(m1, tm1);
        float a0 = __expf(m0 - nm0), a1 = __expf(m1 - nm1);
        m0 = nm0; m1 = nm1;

        float ts0 = 0.f, ts1 = 0.f;
#pragma unroll
        for (int n = 0; n < 16; ++n) {
            s[n][0] = __expf(s[n][0] - m0);
            s[n][1] = __expf(s[n][1] - m0);
            s[n][2] = __expf(s[n][2] - m1);
            s[n][3] = __expf(s[n][3] - m1);
            ts0 += s[n][0] + s[n][1];
            ts1 += s[n][2] + s[n][3];
        }
        ts0 += __shfl_xor_sync(FULL, ts0, 1);
        ts0 += __shfl_xor_sync(FULL, ts0, 2);
        ts1 += __shfl_xor_sync(FULL, ts1, 1);
        ts1 += __shfl_xor_sync(FULL, ts1, 2);
        l0 = l0 * a0 + ts0;
        l1 = l1 * a1 + ts1;
#pragma unroll
        for (int n = 0; n < 16; ++n) {
            o[n][0] *= a0; o[n][1] *= a0;
            o[n][2] *= a1; o[n][3] *= a1;
        }

        // ---- O += P @ V (P via shuffles; V scalar LDS, conflict-free)
        const int bse = lane & 28;
        const int sl0 = bse + (t4 >> 1);
        const int sl1 = sl0 + 2;
        const bool odd = (t4 & 1);
#pragma unroll
        for (int n = 0; n < 16; ++n) {
            float pa = __shfl_sync(FULL, s[n][0], sl0);
            float pb = __shfl_sync(FULL, s[n][1], sl0);
            float pc = __shfl_sync(FULL, s[n][2], sl0);
            float pd = __shfl_sync(FULL, s[n][3], sl0);
            float pe = __shfl_sync(FULL, s[n][0], sl1);
            float pf = __shfl_sync(FULL, s[n][1], sl1);
            float pg = __shfl_sync(FULL, s[n][2], sl1);
            float ph = __shfl_sync(FULL, s[n][3], sl1);
            uint32_t af[4];
            af[0] = __float_as_uint(to_tf32(odd ? pb : pa));
            af[1] = __float_as_uint(to_tf32(odd ? pd : pc));
            af[2] = __float_as_uint(to_tf32(odd ? pf : pe));
            af[3] = __float_as_uint(to_tf32(odd ? ph : pg));
            int kk = n * 8;
#pragma unroll
            for (int nn = 0; nn < 16; ++nn) {
                uint32_t bf[2];
                bf[0] = __float_as_uint(smem[VS_OFF + (kk + t4) * VST + nn * 8 + g]);
                bf[1] = __float_as_uint(smem[VS_OFF + (kk + t4 + 4) * VST + nn * 8 + g]);
                mma8(o[nn], af, bf);
            }
        }
    }

    // ---- normalize + write tf32-rounded (feeds output projection pre-converted)
    float inv0 = 1.f / l0, inv1 = 1.f / l1;
#pragma unroll
    for (int nn = 0; nn < 16; ++nn) {
        int c = h * HD + nn * 8 + (t4 << 1);
        float2 v;
        v.x = to_tf32(o[nn][0] * inv0); v.y = to_tf32(o[nn][1] * inv0);
        *reinterpret_cast<float2*>(Oa + (size_t)r0g * DM + c) = v;
        v.x = to_tf32(o[nn][2] * inv1); v.y = to_tf32(o[nn][3] * inv1);
        *reinterpret_cast<float2*>(Oa + (size_t)(r0g + 8) * DM + c) = v;
    }
}

extern "C" void kernel_launch(void* const* d_in, const int* in_sizes, int n_in,
                              void* d_out, int out_size)
{
    (void)in_sizes; (void)n_in; (void)out_size;
    const float* x  = (const float*)d_in[0];
    const float* wq = (const float*)d_in[1];
    const float* wk = (const float*)d_in[2];
    const float* wv = (const float*)d_in[3];
    const float* wo = (const float*)d_in[4];
    const float* fc = (const float*)d_in[5];
    const float* fs = (const float*)d_in[6];
    // d_in[7] (mask) handled analytically as causal; d_in[8] (start_pos) == 0.
    float* out = (float*)d_out;

    float *q, *k, *v, *att, *xc, *wt;
    cudaGetSymbolAddress((void**)&q,   g_q);
    cudaGetSymbolAddress((void**)&k,   g_k);
    cudaGetSymbolAddress((void**)&v,   g_v);
    cudaGetSymbolAddress((void**)&att, g_att);
    cudaGetSymbolAddress((void**)&xc,  g_xc);
    cudaGetSymbolAddress((void**)&wt,  g_wt);

    cudaFuncSetAttribute(gemm_lm<true, true>,
                         cudaFuncAttributeMaxDynamicSharedMemorySize, GEMM_DSMEM);
    cudaFuncSetAttribute(gemm_lm<false, true>,
                         cudaFuncAttributeMaxDynamicSharedMemorySize, GEMM_DSMEM);
    cudaFuncSetAttribute(gemm_lm<false, false>,
                         cudaFuncAttributeMaxDynamicSharedMemorySize, GEMM_DSMEM);
    cudaFuncSetAttribute(attn_fused,
                         cudaFuncAttributeMaxDynamicSharedMemorySize, ATN_SMEM);

    const dim3 blk(256);
    const dim3 gproj(DM / 128, SQ / 128, 1);    // (32, 16)
    const dim3 gtr(DM / 32, DM / 32, 1);        // (128, 128)
    const dim3 btr(32, 8, 1);

    // Pre-convert x once (reused by Q,K,V projections)
    conv_tf32<<<(SQ * DM / 4) / 256, 256>>>((const float4*)x, (float4*)xc);

    // Q projection (RoPE fused)
    transpose_tf32<<<gtr, btr>>>(wq, wt);
    gemm_lm<true, true><<<gproj, blk, GEMM_DSMEM>>>(xc, wt, q, fc, fs);

    // K projection (RoPE fused)
    transpose_tf32<<<gtr, btr>>>(wk, wt);
    gemm_lm<true, true><<<gproj, blk, GEMM_DSMEM>>>(xc, wt, k, fc, fs);

    // V projection
    transpose_tf32<<<gtr, btr>>>(wv, wt);
    gemm_lm<false, true><<<gproj, blk, GEMM_DSMEM>>>(xc, wt, v, nullptr, nullptr);

    // Fused causal attention (writes tf32-rounded att)
    attn_fused<<<dim3(SQ / 128, NH), blk, ATN_SMEM>>>(q, k, v, att);

    // Output projection (full-precision fp32 output)
    transpose_tf32<<<gtr, btr>>>(wo, wt);
    gemm_lm<false, false><<<gproj, blk, GEMM_DSMEM>>>(att, wt, out, nullptr, nullptr);
}